// round 7
// baseline (speedup 1.0000x reference)
#include <cuda_runtime.h>
#include <stdint.h>

// Problem constants (fixed shapes per reference)
constexpr int D      = 256;    // IN_CHANNELS
constexpr int NPER   = 100;    // nodes per graph
constexpr int KSEL   = 50;     // ceil(0.5 * 100)
constexpr int NGRAPH = 1000;   // 100000 / 100

// out layout (float32, 150000 elems):
//   [0      , 50000)  node_index  (as float)
//   [50000  , 100000) cluster_index (= arange)
//   [100000 , 150000) weight (scores of selected nodes)

__global__ __launch_bounds__(256) void selectsparse_kernel(
    const float* __restrict__ x,
    const float* __restrict__ W,
    const float* __restrict__ b,
    float* __restrict__ out)
{
    __shared__ float s_scores[NPER];

    const int g    = blockIdx.x;
    const int tid  = threadIdx.x;
    const int lane = tid & 31;
    const int warp = tid >> 5;

    // Lane-contiguous W slice: lane l owns float4 chunks l and l+32.
    // (Matches the coalesced row loads below; W is tiny and L2-hot.)
    const float4 w0 = reinterpret_cast<const float4*>(W)[lane];
    const float4 w1 = reinterpret_cast<const float4*>(W)[lane + 32];
    const float bias = b[0];

    const float4* xg = reinterpret_cast<const float4*>(x + (size_t)g * NPER * D);

    // Warp w handles node pair {2w+16t, 2w+16t+1}; NPER=100 is even so both
    // rows are always valid -> all 4 LDG.128 are unconditional and fully
    // coalesced (lanes consecutive 16B, 512B span = 4 wavefronts/request).
    for (int n = warp * 2; n < NPER; n += 16) {
        const float4* rowA = xg + n * (D / 4);
        const float4* rowB = rowA + (D / 4);
        float4 a0 = rowA[lane];
        float4 a1 = rowA[lane + 32];
        float4 b0 = rowB[lane];
        float4 b1 = rowB[lane + 32];
        float sA = a0.x * w0.x + a0.y * w0.y + a0.z * w0.z + a0.w * w0.w
                 + a1.x * w1.x + a1.y * w1.y + a1.z * w1.z + a1.w * w1.w;
        float sB = b0.x * w0.x + b0.y * w0.y + b0.z * w0.z + b0.w * w0.w
                 + b1.x * w1.x + b1.y * w1.y + b1.z * w1.z + b1.w * w1.w;
        #pragma unroll
        for (int o = 16; o > 0; o >>= 1) {
            sA += __shfl_xor_sync(0xffffffffu, sA, o);
            sB += __shfl_xor_sync(0xffffffffu, sB, o);
        }
        if (lane == 0) {
            s_scores[n]     = sA + bias;
            s_scores[n + 1] = sB + bias;
        }
    }
    __syncthreads();   // the ONLY barrier

    // Rank selection: rank(t) = #{j ordered before t} under descending score
    // with ascending-index tie-break -> unique rank in [0,100), identical
    // ordering to lax.top_k. rank < 50 -> emit at slot rank.
    if (tid < NPER) {
        const float st = s_scores[tid];
        int r = 0;
        #pragma unroll 4
        for (int j = 0; j < NPER; j++) {
            const float sj = s_scores[j];   // broadcast LDS, conflict-free
            r += (sj > st) | ((sj == st) & (j < tid));
        }
        if (r < KSEL) {
            const int node = g * NPER + tid;
            const int cl   = g * KSEL + r;
            out[cl]                     = (float)node;
            out[NGRAPH * KSEL + cl]     = (float)cl;
            out[2 * NGRAPH * KSEL + cl] = st;
        }
    }
}

extern "C" void kernel_launch(void* const* d_in, const int* in_sizes, int n_in,
                              void* d_out, int out_size) {
    // Identify inputs by element count (robust to metadata ordering):
    //   x: 25,600,000 f32 | batch: 100,000 (unused) | W: 256 | b: 1
    const float* x = nullptr;
    const float* W = nullptr;
    const float* b = nullptr;
    for (int i = 0; i < n_in; i++) {
        if      (in_sizes[i] == NGRAPH * NPER * D) x = (const float*)d_in[i];
        else if (in_sizes[i] == D)                 W = (const float*)d_in[i];
        else if (in_sizes[i] == 1)                 b = (const float*)d_in[i];
    }
    if (!x) x = (const float*)d_in[0];
    if (!W) W = (const float*)d_in[2];
    if (!b) b = (const float*)d_in[3];
    (void)out_size;
    selectsparse_kernel<<<NGRAPH, 256>>>(x, W, b, (float*)d_out);
}

// round 8
// speedup vs baseline: 1.1113x; 1.1113x over previous
#include <cuda_runtime.h>
#include <stdint.h>

// Problem constants (fixed shapes per reference)
constexpr int D      = 256;    // IN_CHANNELS
constexpr int NPER   = 100;    // nodes per graph
constexpr int KSEL   = 50;     // ceil(0.5 * 100)
constexpr int NGRAPH = 1000;   // 100000 / 100

// out layout (float32, 150000 elems):
//   [0      , 50000)  node_index  (as float)
//   [50000  , 100000) cluster_index (= arange)
//   [100000 , 150000) weight (scores of selected nodes)

__global__ __launch_bounds__(256) void selectsparse_kernel(
    const float* __restrict__ x,
    const float* __restrict__ W,
    const float* __restrict__ b,
    float* __restrict__ out)
{
    __shared__ float s_scores[NPER];

    const int g    = blockIdx.x;
    const int tid  = threadIdx.x;
    const int lane = tid & 31;
    const int warp = tid >> 5;

    // R6-proven W slice layout: lane l owns float4 chunks 2l and 2l+1.
    const float4 w0 = reinterpret_cast<const float4*>(W)[lane * 2 + 0];
    const float4 w1 = reinterpret_cast<const float4*>(W)[lane * 2 + 1];
    const float bias = b[0];

    const float4* xg = reinterpret_cast<const float4*>(x + (size_t)g * NPER * D);

    // Warp w handles the 4-row block {4w, 4w+1, 4w+2, 4w+3}, striding by 32.
    // 100 % 4 == 0 and base <= 96, so all 4 rows are ALWAYS valid:
    // 8 unconditional LDG.128 per lane in flight before any consumption (MLP=8).
    for (int base = warp * 4; base < NPER; base += 32) {
        const float4* r0 = xg + (base + 0) * (D / 4);
        const float4* r1 = xg + (base + 1) * (D / 4);
        const float4* r2 = xg + (base + 2) * (D / 4);
        const float4* r3 = xg + (base + 3) * (D / 4);
        float4 a0 = r0[lane * 2], a1 = r0[lane * 2 + 1];
        float4 b0 = r1[lane * 2], b1 = r1[lane * 2 + 1];
        float4 c0 = r2[lane * 2], c1 = r2[lane * 2 + 1];
        float4 d0 = r3[lane * 2], d1 = r3[lane * 2 + 1];

        float s0 = a0.x * w0.x + a0.y * w0.y + a0.z * w0.z + a0.w * w0.w
                 + a1.x * w1.x + a1.y * w1.y + a1.z * w1.z + a1.w * w1.w;
        float s1 = b0.x * w0.x + b0.y * w0.y + b0.z * w0.z + b0.w * w0.w
                 + b1.x * w1.x + b1.y * w1.y + b1.z * w1.z + b1.w * w1.w;
        float s2 = c0.x * w0.x + c0.y * w0.y + c0.z * w0.z + c0.w * w0.w
                 + c1.x * w1.x + c1.y * w1.y + c1.z * w1.z + c1.w * w1.w;
        float s3 = d0.x * w0.x + d0.y * w0.y + d0.z * w0.z + d0.w * w0.w
                 + d1.x * w1.x + d1.y * w1.y + d1.z * w1.z + d1.w * w1.w;

        // 4 interleaved butterfly chains: per level the 4 shfls are
        // independent, so latency is amortized across rows.
        #pragma unroll
        for (int o = 16; o > 0; o >>= 1) {
            s0 += __shfl_xor_sync(0xffffffffu, s0, o);
            s1 += __shfl_xor_sync(0xffffffffu, s1, o);
            s2 += __shfl_xor_sync(0xffffffffu, s2, o);
            s3 += __shfl_xor_sync(0xffffffffu, s3, o);
        }
        if (lane == 0) {
            s_scores[base + 0] = s0 + bias;
            s_scores[base + 1] = s1 + bias;
            s_scores[base + 2] = s2 + bias;
            s_scores[base + 3] = s3 + bias;
        }
    }
    __syncthreads();   // the ONLY barrier

    // Rank selection: rank(t) = #{j ordered before t} under descending score
    // with ascending-index tie-break -> unique rank in [0,100), identical
    // ordering to lax.top_k. rank < 50 -> emit at slot rank.
    if (tid < NPER) {
        const float st = s_scores[tid];
        int r = 0;
        #pragma unroll 4
        for (int j = 0; j < NPER; j++) {
            const float sj = s_scores[j];   // broadcast LDS, conflict-free
            r += (sj > st) | ((sj == st) & (j < tid));
        }
        if (r < KSEL) {
            const int node = g * NPER + tid;
            const int cl   = g * KSEL + r;
            out[cl]                     = (float)node;
            out[NGRAPH * KSEL + cl]     = (float)cl;
            out[2 * NGRAPH * KSEL + cl] = st;
        }
    }
}

extern "C" void kernel_launch(void* const* d_in, const int* in_sizes, int n_in,
                              void* d_out, int out_size) {
    // Identify inputs by element count (robust to metadata ordering):
    //   x: 25,600,000 f32 | batch: 100,000 (unused) | W: 256 | b: 1
    const float* x = nullptr;
    const float* W = nullptr;
    const float* b = nullptr;
    for (int i = 0; i < n_in; i++) {
        if      (in_sizes[i] == NGRAPH * NPER * D) x = (const float*)d_in[i];
        else if (in_sizes[i] == D)                 W = (const float*)d_in[i];
        else if (in_sizes[i] == 1)                 b = (const float*)d_in[i];
    }
    if (!x) x = (const float*)d_in[0];
    if (!W) W = (const float*)d_in[2];
    if (!b) b = (const float*)d_in[3];
    (void)out_size;
    selectsparse_kernel<<<NGRAPH, 256>>>(x, W, b, (float*)d_out);
}